// round 16
// baseline (speedup 1.0000x reference)
#include <cuda_runtime.h>
#include <cuda_fp16.h>
#include <math.h>
#include <stdint.h>

#define NN   50000
#define NV   50001
#define NPAD 50048      // 782 * 64
#define NE   400000
#define IND  256
#define HID  128
#define C2   256
#define OD   64
#define WTOT 139264
#define SCHUNK 1024
#define SNB   49
#define L2E  1.4426950408889634f

typedef unsigned long long u64;

// ---------------- static device scratch -------------------------------------
__device__ __half g_A[(size_t)NPAD * IND];    // fp16 GEMM A input
__device__ __half g_Bt[WTOT];                 // fp16 B^T (N-major, k-contig)
__device__ __half g_hh[(size_t)NV * C2];      // transformed features (PERMUTED cols)
__device__ float g_as[NV * 2];
__device__ float g_ad[NV * 2];
__device__ int   g_cnt[SNB * SCHUNK];
__device__ int   g_cur[NV];
__device__ int   g_scan[SNB * SCHUNK];
__device__ int   g_btot[SNB];
__device__ int   g_boff[SNB];
__device__ int   g_sdone;
__device__ int   g_srcsorted[NE];
__device__ float g_colpart[256 * 256];
__device__ uint32_t g_asmax[3][2];
__device__ float g_vS[C2];
__device__ float g_vden[2];
__device__ int   g_vdone;

__device__ __forceinline__ float lrelu(float x) { return x > 0.f ? x : 0.2f * x; }

__device__ __forceinline__ uint32_t fkey(float f) {
    uint32_t b = __float_as_uint(f);
    return b ^ (uint32_t)(((int)b >> 31) | (int)0x80000000);
}
__device__ __forceinline__ float funkey(uint32_t k) {
    uint32_t b = (k & 0x80000000u) ? (k ^ 0x80000000u) : ~k;
    return __uint_as_float(b);
}

__device__ __forceinline__ uint32_t smem_to_u32(const void* p) {
    uint32_t a;
    asm("{ .reg .u64 t; cvta.to.shared.u64 t, %1; cvt.u32.u64 %0, t; }" : "=r"(a) : "l"(p));
    return a;
}

// ---- packed f32x2 helpers ---------------------------------------------------
__device__ __forceinline__ float ex2f(float x) {
    float y; asm("ex2.approx.f32 %0, %1;" : "=f"(y) : "f"(x)); return y;
}
__device__ __forceinline__ u64 pk2(float lo, float hi) {
    u64 r; asm("mov.b64 %0, {%1,%2};" : "=l"(r) : "f"(lo), "f"(hi)); return r;
}
__device__ __forceinline__ void upk2(u64 v, float& lo, float& hi) {
    asm("mov.b64 {%0,%1}, %2;" : "=f"(lo), "=f"(hi) : "l"(v));
}
__device__ __forceinline__ void fma2p(u64& a, u64 q, u64 c) {
    asm("fma.rn.f32x2 %0, %1, %2, %3;" : "=l"(a) : "l"(q), "l"(c), "l"(a));
}
__device__ __forceinline__ u64 h2f2(uint32_t h) {
    float2 f = __half22float2(*(__half2*)&h);
    return pk2(f.x, f.y);
}

#define SW128(off) ((off) ^ (((off) >> 3) & 0x70))

#define LDSM_X4(r0, r1, r2, r3, addr) \
    asm volatile("ldmatrix.sync.aligned.m8n8.x4.shared.b16 {%0,%1,%2,%3}, [%4];" \
        : "=r"(r0), "=r"(r1), "=r"(r2), "=r"(r3) : "r"(addr))

#define CP16(s, g) asm volatile("cp.async.cg.shared.global [%0], [%1], 16;" :: "r"(s), "l"(g))
#define CPCOMMIT() asm volatile("cp.async.commit_group;" ::: "memory")

__device__ __forceinline__ void mma16816(float* c, const uint32_t* a, uint32_t b0, uint32_t b1) {
    asm volatile("mma.sync.aligned.m16n8k16.row.col.f32.f16.f16.f32 "
        "{%0,%1,%2,%3}, {%4,%5,%6,%7}, {%8,%9}, {%0,%1,%2,%3};"
        : "+f"(c[0]), "+f"(c[1]), "+f"(c[2]), "+f"(c[3])
        : "r"(a[0]), "r"(a[1]), "r"(a[2]), "r"(a[3]), "r"(b0), "r"(b1));
}

// ---------------- setup ------------------------------------------------------
__global__ void k_setup(const float* __restrict__ X, const int* __restrict__ ei,
                        const float* __restrict__ W0, const float* __restrict__ W1,
                        const float* __restrict__ W2, const float* __restrict__ Wo) {
    if (blockIdx.x >= 1280) {
        int i = (blockIdx.x - 1280) * 256 + threadIdx.x;
        const float* W; int K, Ncol, off, loc;
        if      (i < 65536)  { W = W0; K = 256; Ncol = 256; off = 0;      loc = i; }
        else if (i < 98304)  { W = W1; K = 128; Ncol = 256; off = 65536;  loc = i - 65536; }
        else if (i < 131072) { W = W2; K = 128; Ncol = 256; off = 98304;  loc = i - 98304; }
        else if (i < WTOT)   { W = Wo; K = 128; Ncol = 64;  off = 131072; loc = i - 131072; }
        else return;
        int n = loc / K, k = loc % K;
        g_Bt[off + n * K + k] = __float2half(W[k * Ncol + n]);
        return;
    }
    if (blockIdx.x >= 256) {
        int i = (blockIdx.x - 256) * 256 + threadIdx.x;
        int stride = 1024 * 256;
        for (int e = i; e < NE; e += stride)
            atomicAdd(&g_cnt[ei[NE + e]], 1);
        return;
    }
    int c = threadIdx.x, b = blockIdx.x;
    if (b == 0 && c < 6) (&g_asmax[0][0])[c] = 0;
    float s = 0.f;
    for (int r = b; r < NN; r += 256) {
        float v = X[(size_t)r * IND + c];
        g_A[(size_t)r * IND + c] = __float2half(v);
        s += v;
    }
    g_colpart[b * 256 + c] = s;
}

// ---------------- CSR scan + level-2 + vnode row -----------------------------
__global__ void k_scan1() {        // (SNB+1) x 1024
    if (blockIdx.x == SNB) {
        int c = threadIdx.x;
        if (c < 256) {
            float s = 0.f;
            for (int p = 0; p < 256; p++) s += g_colpart[p * 256 + c];
            g_A[(size_t)NN * IND + c] = __float2half(s * (1.0f / NN));
        }
        return;
    }
    int b = blockIdx.x, t = threadIdx.x, lane = t & 31, w = t >> 5;
    int idx = b * SCHUNK + t;
    int v = g_cnt[idx];
    g_cnt[idx] = 0;
    if (idx < NV) g_cur[idx] = 0;
    int x = v;
#pragma unroll
    for (int off = 1; off < 32; off <<= 1) {
        int y = __shfl_up_sync(0xffffffffu, x, off);
        if (lane >= off) x += y;
    }
    __shared__ int wt[32];
    if (lane == 31) wt[w] = x;
    __syncthreads();
    if (w == 0) {
        int z = wt[lane];
#pragma unroll
        for (int off = 1; off < 32; off <<= 1) {
            int y = __shfl_up_sync(0xffffffffu, z, off);
            if (lane >= off) z += y;
        }
        wt[lane] = z;
    }
    __syncthreads();
    int excl = x - v + (w ? wt[w - 1] : 0);
    g_scan[idx] = excl;
    if (t == 0) {
        g_btot[b] = wt[31];
        __threadfence();
        if (atomicAdd(&g_sdone, 1) == SNB - 1) {
            int acc = 0;
            for (int i = 0; i < SNB; i++) { g_boff[i] = acc; acc += g_btot[i]; }
            g_sdone = 0;
        }
    }
}

__device__ __forceinline__ int rowptr_of(int i) {
    return g_scan[i] + g_boff[i >> 10];
}

// ---------------- HMMA GEMM --------------------------------------------------
// HOUT path stores h with PERMUTED columns: feature f of head h goes to
// position (f>>2)*8 + h*4 + (f&3), so lane L's 8 agg values are 16B-contiguous.
template<int KTOT, int NTB, bool ALPHA, bool HOUT, bool FUSEFILL>
__global__ void __launch_bounds__(256, 2) k_hgemm(
    const __half* __restrict__ A, const __half* __restrict__ Bt,
    void* __restrict__ Cout, int M,
    const float* __restrict__ aws, const float* __restrict__ awd,
    const float* __restrict__ bias, uint32_t* __restrict__ asmax,
    const int* __restrict__ ei, int nblk)
{
    constexpr int NCH = KTOT / 64;
    constexpr int NTW = (NTB / 4) / 8;
    constexpr int NJP = NTW / 2;
    constexpr int STAGE = 8192 + NTB * 128;

    if (FUSEFILL && (int)blockIdx.x >= nblk) {
        int i = ((int)blockIdx.x - nblk) * 256 + threadIdx.x;
        int stride = 1024 * 256;
        for (int e = i; e < NE; e += stride) {
            int s = ei[e];
            int d = ei[NE + e];
            int pos = rowptr_of(d) + atomicAdd(&g_cur[d], 1);
            g_srcsorted[pos] = s;
        }
        return;
    }

    extern __shared__ char smem[];
    uint32_t sb = smem_to_u32(smem);
    int tid = threadIdx.x, wid = tid >> 5, lane = tid & 31;
    int wm = wid >> 2, wn = wid & 3;
    int row0 = blockIdx.x * 64;

    float acc[2][NTW][4];
#pragma unroll
    for (int mt = 0; mt < 2; mt++)
#pragma unroll
        for (int nt = 0; nt < NTW; nt++)
#pragma unroll
            for (int j = 0; j < 4; j++) acc[mt][nt][j] = 0.f;

    int lmrow = ((lane >> 3) & 1) * 8 + (lane & 7);
    uint32_t akoff = ((lane >> 4) & 1) * 16;
    int bnrow = wn * (NTB / 4) + ((lane >> 4) & 1) * 8 + (lane & 7);
    uint32_t bkoff = ((lane >> 3) & 1) * 16;

    for (int ch = 0; ch <= NCH; ch++) {
        if (ch < NCH) {
            uint32_t base = sb + (uint32_t)(ch & 1) * STAGE;
            for (int u = tid; u < 512; u += 256) {
                int r = u >> 3, c8 = u & 7;
                size_t gidx = (size_t)(row0 + r) * KTOT + ch * 64 + c8 * 8;
                CP16(base + SW128((uint32_t)(r * 128 + c8 * 16)), A + gidx);
            }
            for (int u = tid; u < NTB * 8; u += 256) {
                int r = u >> 3, c8 = u & 7;
                size_t gidx = (size_t)r * KTOT + ch * 64 + c8 * 8;
                CP16(base + 8192 + SW128((uint32_t)(r * 128 + c8 * 16)), Bt + gidx);
            }
            CPCOMMIT();
        }
        if (ch == 0) continue;
        if (ch < NCH) asm volatile("cp.async.wait_group 1;" ::: "memory");
        else         asm volatile("cp.async.wait_group 0;" ::: "memory");
        __syncthreads();
        uint32_t ab = sb + (uint32_t)((ch - 1) & 1) * STAGE;
#pragma unroll
        for (int ks = 0; ks < 4; ks++) {
            uint32_t ah[2][4];
#pragma unroll
            for (int mt = 0; mt < 2; mt++) {
                uint32_t aaddr = ab + SW128((uint32_t)((wm * 32 + mt * 16 + lmrow) * 128 + ks * 32 + akoff));
                LDSM_X4(ah[mt][0], ah[mt][1], ah[mt][2], ah[mt][3], aaddr);
            }
#pragma unroll
            for (int jp = 0; jp < NJP; jp++) {
                uint32_t baddr = ab + 8192 + SW128((uint32_t)((bnrow + jp * 16) * 128 + ks * 32 + bkoff));
                uint32_t b0, b1, b2, b3;
                LDSM_X4(b0, b1, b2, b3, baddr);
#pragma unroll
                for (int mt = 0; mt < 2; mt++) {
                    mma16816(acc[mt][2 * jp],     ah[mt], b0, b1);
                    mma16816(acc[mt][2 * jp + 1], ah[mt], b2, b3);
                }
            }
        }
        __syncthreads();
    }

    // ---- epilogue ----
    float* sAs = (float*)smem;          // [64][4]
    float* sAd = sAs + 256;             // [64][4]
    float* sMx = sAd + 256;             // [16]
    int g = lane >> 2, t = lane & 3;
#pragma unroll
    for (int mt = 0; mt < 2; mt++) {
        int r0 = wm * 32 + mt * 16 + g;
        int gr0 = row0 + r0, gr1 = gr0 + 8;
        float pa0 = 0.f, pa1 = 0.f, pd0 = 0.f, pd1 = 0.f;
#pragma unroll
        for (int nt = 0; nt < NTW; nt++) {
            int gc = wn * (NTB / 4) + nt * 8 + t * 2;
            float c0 = acc[mt][nt][0], c1 = acc[mt][nt][1];
            float c2 = acc[mt][nt][2], c3 = acc[mt][nt][3];
            if (!ALPHA) {
                float b0 = bias[gc], b1 = bias[gc + 1];
                c0 += b0; c1 += b1; c2 += b0; c3 += b1;
            }
            if (ALPHA) {
                float w0s = aws[gc], w1s = aws[gc + 1], w0d = awd[gc], w1d = awd[gc + 1];
                pa0 += c0 * w0s + c1 * w1s; pd0 += c0 * w0d + c1 * w1d;
                pa1 += c2 * w0s + c3 * w1s; pd1 += c2 * w0d + c3 * w1d;
            }
            if (HOUT) {
                // permuted store: f=gc&127, h=gc>>7 -> pos=(f>>2)*8 + h*4 + (f&3)
                int f = gc & 127, hh = gc >> 7;
                int pos = ((f >> 2) << 3) + (hh << 2) + (f & 3);
                __half* Ch = (__half*)Cout;
                if (gr0 < M) *(__half2*)(Ch + (size_t)gr0 * NTB + pos) = __floats2half2_rn(c0, c1);
                if (gr1 < M) *(__half2*)(Ch + (size_t)gr1 * NTB + pos) = __floats2half2_rn(c2, c3);
            } else {
                float* Cf = (float*)Cout;
                if (gr0 < M) *(float2*)(Cf + (size_t)gr0 * NTB + gc) = make_float2(c0, c1);
                if (gr1 < M) *(float2*)(Cf + (size_t)gr1 * NTB + gc) = make_float2(c2, c3);
            }
        }
        if (ALPHA) {
#pragma unroll
            for (int off = 1; off <= 2; off <<= 1) {
                pa0 += __shfl_xor_sync(0xffffffffu, pa0, off);
                pa1 += __shfl_xor_sync(0xffffffffu, pa1, off);
                pd0 += __shfl_xor_sync(0xffffffffu, pd0, off);
                pd1 += __shfl_xor_sync(0xffffffffu, pd1, off);
            }
            if (t == 0) {
                sAs[r0 * 4 + wn] = pa0; sAs[(r0 + 8) * 4 + wn] = pa1;
                sAd[r0 * 4 + wn] = pd0; sAd[(r0 + 8) * 4 + wn] = pd1;
            }
        }
    }
    if (ALPHA) {
        __syncthreads();
        float lm0 = -3.4e38f, lm1 = -3.4e38f;
        if (tid < 64) {
            int row = row0 + tid;
            float as0 = sAs[tid * 4 + 0] + sAs[tid * 4 + 1];
            float as1 = sAs[tid * 4 + 2] + sAs[tid * 4 + 3];
            float ad0 = sAd[tid * 4 + 0] + sAd[tid * 4 + 1];
            float ad1 = sAd[tid * 4 + 2] + sAd[tid * 4 + 3];
            if (row < M) {
                g_as[2 * row] = as0; g_as[2 * row + 1] = as1;
                g_ad[2 * row] = ad0; g_ad[2 * row + 1] = ad1;
                lm0 = as0; lm1 = as1;
            }
        }
#pragma unroll
        for (int off = 16; off; off >>= 1) {
            lm0 = fmaxf(lm0, __shfl_xor_sync(0xffffffffu, lm0, off));
            lm1 = fmaxf(lm1, __shfl_xor_sync(0xffffffffu, lm1, off));
        }
        if (lane == 0 && wid < 2) { sMx[wid] = lm0; sMx[8 + wid] = lm1; }
        __syncthreads();
        if (tid == 0) {
            float m0 = fmaxf(sMx[0], sMx[1]);
            float m1 = fmaxf(sMx[8], sMx[9]);
            atomicMax(asmax + 0, fkey(m0));
            atomicMax(asmax + 1, fkey(m1));
        }
    }
}

// ---------------- merged vnode + node aggregation ----------------------------
// h layout permuted: uint4 at (node*C2 + 8*lane): x,y = head0 f(4L..4L+3),
// z,w = head1 f(4L..4L+3). Edge coefs computed lane-parallel, shfl-broadcast.
#define VB 256
__global__ void k_agg(int l, const float* __restrict__ b,
                      const float* __restrict__ gam, const float* __restrict__ bet) {
    int tid = threadIdx.x, wid = tid >> 5, lane = tid & 31;
    float m0g = funkey(g_asmax[l][0]), m1g = funkey(g_asmax[l][1]);

    if (blockIdx.x < VB) {
        float adv0 = g_ad[2 * NN], adv1 = g_ad[2 * NN + 1];
        float adl0 = adv0 * L2E, adl1 = adv1 * L2E;
        float mlog0 = lrelu(m0g + adv0) * L2E, mlog1 = lrelu(m1g + adv1) * L2E;
        int gw = blockIdx.x * 8 + wid;
        u64 A0 = 0, A1 = 0, A2 = 0, A3 = 0;
        float den0 = 0.f, den1 = 0.f;
        for (int j = gw; j < NV; j += VB * 8) {
            float t0 = fmaf(g_as[2 * j], L2E, adl0);
            float t1 = fmaf(g_as[2 * j + 1], L2E, adl1);
            t0 = fmaxf(t0, 0.2f * t0); t1 = fmaxf(t1, 0.2f * t1);
            float e0 = ex2f(t0 - mlog0), e1 = ex2f(t1 - mlog1);
            den0 += e0; den1 += e1;
            u64 C0 = pk2(e0, e0), C1 = pk2(e1, e1);
            uint4 u = *(const uint4*)(g_hh + (size_t)j * C2 + 8 * lane);
            fma2p(A0, h2f2(u.x), C0); fma2p(A1, h2f2(u.y), C0);
            fma2p(A2, h2f2(u.z), C1); fma2p(A3, h2f2(u.w), C1);
        }
        float a0x, a0y, a0z, a0w, a1x, a1y, a1z, a1w;
        upk2(A0, a0x, a0y); upk2(A1, a0z, a0w);
        upk2(A2, a1x, a1y); upk2(A3, a1z, a1w);
        __shared__ float buf[C2];
        __shared__ float sden[2];
        if (tid < C2) buf[tid] = 0.f;
        if (tid < 2) sden[tid] = 0.f;
        __syncthreads();
        atomicAdd(&buf[4 * lane + 0], a0x); atomicAdd(&buf[4 * lane + 1], a0y);
        atomicAdd(&buf[4 * lane + 2], a0z); atomicAdd(&buf[4 * lane + 3], a0w);
        atomicAdd(&buf[128 + 4 * lane + 0], a1x); atomicAdd(&buf[128 + 4 * lane + 1], a1y);
        atomicAdd(&buf[128 + 4 * lane + 2], a1z); atomicAdd(&buf[128 + 4 * lane + 3], a1w);
        if (lane == 0) { atomicAdd(&sden[0], den0); atomicAdd(&sden[1], den1); }
        __syncthreads();
        if (tid < C2) atomicAdd(&g_vS[tid], buf[tid]);
        if (tid < 2) atomicAdd(&g_vden[tid], sden[tid]);

        __threadfence();
        __shared__ int slast;
        if (tid == 0) slast = (atomicAdd(&g_vdone, 1) == VB - 1);
        __syncthreads();
        if (!slast) return;

        int o = tid;
        float v = 0.f;
        if (o < 128) {
            float d0 = g_vden[0] + 1e-16f, d1 = g_vden[1] + 1e-16f;
            v = 0.5f * (g_vS[o] / d0 + g_vS[HID + o] / d1) + b[o];
        }
        __shared__ float ssum[8], ssq[8];
        float ls = (o < 128) ? v : 0.f, lq = (o < 128) ? v * v : 0.f;
#pragma unroll
        for (int off = 16; off; off >>= 1) {
            ls += __shfl_xor_sync(0xffffffffu, ls, off);
            lq += __shfl_xor_sync(0xffffffffu, lq, off);
        }
        if (lane == 0) { ssum[wid] = ls; ssq[wid] = lq; }
        __syncthreads();
        float ts = ssum[0] + ssum[1] + ssum[2] + ssum[3];
        float tq = ssq[0] + ssq[1] + ssq[2] + ssq[3];
        float mu = ts * (1.0f / HID);
        float var = tq * (1.0f / HID) - mu * mu;
        if (o < 128) {
            float y = (v - mu) * rsqrtf(var + 1e-5f) * gam[o] + bet[o];
            y = 0.5f * y * (1.f + erff(y * 0.70710678118654752f));
            g_A[(size_t)NN * HID + o] = __float2half(y);
        }
        __syncthreads();
        if (o < C2) g_vS[o] = 0.f;
        if (o < 2) g_vden[o] = 0.f;
        if (o == 0) g_vdone = 0;
        return;
    }

    int i = (blockIdx.x - VB) * 8 + wid;
    if (i >= NN) return;
    float ad0 = g_ad[2 * i], ad1 = g_ad[2 * i + 1];
    float adl0 = ad0 * L2E, adl1 = ad1 * L2E;
    float mlog0 = lrelu(m0g + ad0) * L2E, mlog1 = lrelu(m1g + ad1) * L2E;

    u64 A0 = 0, A1 = 0, A2 = 0, A3 = 0;
    float cs0, cs1, cv0, cv1;
    {
        // self loop
        float t0 = fmaf(g_as[2 * i], L2E, adl0);
        float t1 = fmaf(g_as[2 * i + 1], L2E, adl1);
        t0 = fmaxf(t0, 0.2f * t0); t1 = fmaxf(t1, 0.2f * t1);
        cs0 = ex2f(t0 - mlog0); cs1 = ex2f(t1 - mlog1);
        u64 C0 = pk2(cs0, cs0), C1 = pk2(cs1, cs1);
        uint4 u = *(const uint4*)(g_hh + (size_t)i * C2 + 8 * lane);
        fma2p(A0, h2f2(u.x), C0); fma2p(A1, h2f2(u.y), C0);
        fma2p(A2, h2f2(u.z), C1); fma2p(A3, h2f2(u.w), C1);
        // vnode -> node edge
        t0 = fmaf(g_as[2 * NN], L2E, adl0);
        t1 = fmaf(g_as[2 * NN + 1], L2E, adl1);
        t0 = fmaxf(t0, 0.2f * t0); t1 = fmaxf(t1, 0.2f * t1);
        cv0 = ex2f(t0 - mlog0); cv1 = ex2f(t1 - mlog1);
        C0 = pk2(cv0, cv0); C1 = pk2(cv1, cv1);
        uint4 uv = *(const uint4*)(g_hh + (size_t)NN * C2 + 8 * lane);
        fma2p(A0, h2f2(uv.x), C0); fma2p(A1, h2f2(uv.y), C0);
        fma2p(A2, h2f2(uv.z), C1); fma2p(A3, h2f2(uv.w), C1);
    }
    int e = rowptr_of(i), end = rowptr_of(i + 1);
    float dp0 = 0.f, dp1 = 0.f;   // per-lane den partials (edges only)
    while (e < end) {
        int glen = end - e;
        if (glen > 32) glen = 32;
        int myS = 0; float mc0 = 0.f, mc1 = 0.f;
        if (lane < glen) {
            myS = g_srcsorted[e + lane];
            float t0 = fmaf(g_as[2 * myS], L2E, adl0);
            float t1 = fmaf(g_as[2 * myS + 1], L2E, adl1);
            t0 = fmaxf(t0, 0.2f * t0); t1 = fmaxf(t1, 0.2f * t1);
            mc0 = ex2f(t0 - mlog0); mc1 = ex2f(t1 - mlog1);
            dp0 += mc0; dp1 += mc1;
        }
        int sN = __shfl_sync(0xffffffffu, myS, 0);
        uint4 un = *(const uint4*)(g_hh + (size_t)sN * C2 + 8 * lane);
        for (int k = 0; k < glen; k++) {
            uint4 u = un;
            if (k + 1 < glen) {
                sN = __shfl_sync(0xffffffffu, myS, k + 1);
                un = *(const uint4*)(g_hh + (size_t)sN * C2 + 8 * lane);
            }
            float c0 = __shfl_sync(0xffffffffu, mc0, k);
            float c1 = __shfl_sync(0xffffffffu, mc1, k);
            u64 C0 = pk2(c0, c0), C1 = pk2(c1, c1);
            fma2p(A0, h2f2(u.x), C0); fma2p(A1, h2f2(u.y), C0);
            fma2p(A2, h2f2(u.z), C1); fma2p(A3, h2f2(u.w), C1);
        }
        e += glen;
    }
    // butterfly-sum edge den partials; add self + vnode coefs
#pragma unroll
    for (int off = 16; off; off >>= 1) {
        dp0 += __shfl_xor_sync(0xffffffffu, dp0, off);
        dp1 += __shfl_xor_sync(0xffffffffu, dp1, off);
    }
    float den0 = dp0 + cs0 + cv0;
    float den1 = dp1 + cs1 + cv1;

    float a0x, a0y, a0z, a0w, a1x, a1y, a1z, a1w;
    upk2(A0, a0x, a0y); upk2(A1, a0z, a0w);
    upk2(A2, a1x, a1y); upk2(A3, a1z, a1w);

    float inv0 = 0.5f / (den0 + 1e-16f);
    float inv1 = 0.5f / (den1 + 1e-16f);
    float v[4];
    v[0] = a0x * inv0 + a1x * inv1;
    v[1] = a0y * inv0 + a1y * inv1;
    v[2] = a0z * inv0 + a1z * inv1;
    v[3] = a0w * inv0 + a1w * inv1;
    float lsum = 0.f, lsq = 0.f;
#pragma unroll
    for (int r = 0; r < 4; r++) {
        int o = 4 * lane + r;
        v[r] += b[o];
        lsum += v[r];
        lsq = fmaf(v[r], v[r], lsq);
    }
#pragma unroll
    for (int off = 16; off; off >>= 1) {
        lsum += __shfl_xor_sync(0xffffffffu, lsum, off);
        lsq += __shfl_xor_sync(0xffffffffu, lsq, off);
    }
    float mu = lsum * (1.0f / HID);
    float var = lsq * (1.0f / HID) - mu * mu;
    float rstd = rsqrtf(var + 1e-5f);
    __half hs[4];
#pragma unroll
    for (int r = 0; r < 4; r++) {
        int o = 4 * lane + r;
        float y = (v[r] - mu) * rstd * gam[o] + bet[o];
        y = 0.5f * y * (1.f + erff(y * 0.70710678118654752f));
        hs[r] = __float2half(y);
    }
    *(uint2*)&g_A[(size_t)i * HID + 4 * lane] = *(uint2*)hs;
}

// ---------------- host orchestration ----------------------------------------
extern "C" void kernel_launch(void* const* d_in, const int* in_sizes, int n_in,
                              void* d_out, int out_size) {
    const float* X  = (const float*)d_in[0];
    const int*   ei = (const int*)d_in[1];
    const float* W[3]   = { (const float*)d_in[3],  (const float*)d_in[9],  (const float*)d_in[15] };
    const float* a_s[3] = { (const float*)d_in[4],  (const float*)d_in[10], (const float*)d_in[16] };
    const float* a_d[3] = { (const float*)d_in[5],  (const float*)d_in[11], (const float*)d_in[17] };
    const float* bb[3]  = { (const float*)d_in[6],  (const float*)d_in[12], (const float*)d_in[18] };
    const float* gg[3]  = { (const float*)d_in[7],  (const float*)d_in[13], (const float*)d_in[19] };
    const float* be[3]  = { (const float*)d_in[8],  (const float*)d_in[14], (const float*)d_in[20] };
    const float* Wout = (const float*)d_in[21];
    const float* bout = (const float*)d_in[22];

    __half *pA, *pBt, *p_hh;
    uint32_t* p_am;
    cudaGetSymbolAddress((void**)&pA,   g_A);
    cudaGetSymbolAddress((void**)&pBt,  g_Bt);
    cudaGetSymbolAddress((void**)&p_hh, g_hh);
    cudaGetSymbolAddress((void**)&p_am, g_asmax);

    const int SM256 = 2 * (8192 + 256 * 128);   // 81920
    const int SM64  = 2 * (8192 + 64 * 128);    // 32768
    cudaFuncSetAttribute(k_hgemm<256, 256, true,  true,  true>,  cudaFuncAttributeMaxDynamicSharedMemorySize, SM256);
    cudaFuncSetAttribute(k_hgemm<128, 256, true,  true,  false>, cudaFuncAttributeMaxDynamicSharedMemorySize, SM256);
    cudaFuncSetAttribute(k_hgemm<128, 64,  false, false, false>, cudaFuncAttributeMaxDynamicSharedMemorySize, SM64);

    const int NBLK = NPAD / 64;           // 782
    const int AGGB = VB + (NN + 7) / 8;   // 6506
    const int WOFF[4] = { 0, 65536, 98304, 131072 };

    k_setup<<<1825, 256>>>(X, ei, W[0], W[1], W[2], Wout);   // idx 0
    k_scan1<<<SNB + 1, 1024>>>();                            // idx 1
    // layer-0 GEMM fused with CSR fill
    k_hgemm<256, 256, true, true, true><<<NBLK + 1024, 256, SM256>>>(
        pA, pBt + WOFF[0], p_hh, NV, a_s[0], a_d[0], nullptr, p_am + 0, ei, NBLK);  // idx 2
    k_agg<<<AGGB, 256>>>(0, bb[0], gg[0], be[0]);            // idx 3 == profiled

    for (int l = 1; l < 3; l++) {
        k_hgemm<128, 256, true, true, false><<<NBLK, 256, SM256>>>(
            pA, pBt + WOFF[l], p_hh, NV, a_s[l], a_d[l], nullptr, p_am + 2 * l, nullptr, NBLK);
        k_agg<<<AGGB, 256>>>(l, bb[l], gg[l], be[l]);
    }

    k_hgemm<128, 64, false, false, false><<<NBLK, 256, SM64>>>(
        pA, pBt + WOFF[3], (float*)d_out, NN, nullptr, nullptr, bout, nullptr, nullptr, NBLK);
}

// round 17
// speedup vs baseline: 1.0523x; 1.0523x over previous
#include <cuda_runtime.h>
#include <cuda_fp16.h>
#include <math.h>
#include <stdint.h>

#define NN   50000
#define NV   50001
#define NPAD 50048      // 782 * 64
#define NE   400000
#define IND  256
#define HID  128
#define C2   256
#define OD   64
#define WTOT 139264
#define SCHUNK 1024
#define SNB   49
#define L2E  1.4426950408889634f

typedef unsigned long long u64;

// ---------------- static device scratch -------------------------------------
__device__ __half g_A[(size_t)NPAD * IND];    // fp16 GEMM A input
__device__ __half g_Bt[WTOT];                 // fp16 B^T (N-major, k-contig)
__device__ __half g_hh[(size_t)NV * C2];      // transformed features (PERMUTED cols)
__device__ float g_as[NV * 2];
__device__ float g_ad[NV * 2];
__device__ int   g_cnt[SNB * SCHUNK];
__device__ int   g_cur[NV];
__device__ int   g_scan[SNB * SCHUNK];
__device__ int   g_btot[SNB];
__device__ int   g_boff[SNB];
__device__ int   g_sdone;
__device__ int   g_srcsorted[NE];
__device__ float g_colpart[256 * 256];
__device__ uint32_t g_asmax[3][2];
__device__ float g_vS[C2];
__device__ float g_vden[2];
__device__ int   g_vdone;

__device__ __forceinline__ float lrelu(float x) { return x > 0.f ? x : 0.2f * x; }

__device__ __forceinline__ uint32_t fkey(float f) {
    uint32_t b = __float_as_uint(f);
    return b ^ (uint32_t)(((int)b >> 31) | (int)0x80000000);
}
__device__ __forceinline__ float funkey(uint32_t k) {
    uint32_t b = (k & 0x80000000u) ? (k ^ 0x80000000u) : ~k;
    return __uint_as_float(b);
}

__device__ __forceinline__ uint32_t smem_to_u32(const void* p) {
    uint32_t a;
    asm("{ .reg .u64 t; cvta.to.shared.u64 t, %1; cvt.u32.u64 %0, t; }" : "=r"(a) : "l"(p));
    return a;
}

// ---- packed f32x2 helpers ---------------------------------------------------
__device__ __forceinline__ float ex2f(float x) {
    float y; asm("ex2.approx.f32 %0, %1;" : "=f"(y) : "f"(x)); return y;
}
__device__ __forceinline__ u64 pk2(float lo, float hi) {
    u64 r; asm("mov.b64 %0, {%1,%2};" : "=l"(r) : "f"(lo), "f"(hi)); return r;
}
__device__ __forceinline__ void upk2(u64 v, float& lo, float& hi) {
    asm("mov.b64 {%0,%1}, %2;" : "=f"(lo), "=f"(hi) : "l"(v));
}
__device__ __forceinline__ void fma2p(u64& a, u64 q, u64 c) {
    asm("fma.rn.f32x2 %0, %1, %2, %3;" : "=l"(a) : "l"(q), "l"(c), "l"(a));
}
__device__ __forceinline__ u64 h2f2(uint32_t h) {
    float2 f = __half22float2(*(__half2*)&h);
    return pk2(f.x, f.y);
}

#define SW128(off) ((off) ^ (((off) >> 3) & 0x70))

#define LDSM_X4(r0, r1, r2, r3, addr) \
    asm volatile("ldmatrix.sync.aligned.m8n8.x4.shared.b16 {%0,%1,%2,%3}, [%4];" \
        : "=r"(r0), "=r"(r1), "=r"(r2), "=r"(r3) : "r"(addr))

#define CP16(s, g) asm volatile("cp.async.cg.shared.global [%0], [%1], 16;" :: "r"(s), "l"(g))
#define CPCOMMIT() asm volatile("cp.async.commit_group;" ::: "memory")

__device__ __forceinline__ void mma16816(float* c, const uint32_t* a, uint32_t b0, uint32_t b1) {
    asm volatile("mma.sync.aligned.m16n8k16.row.col.f32.f16.f16.f32 "
        "{%0,%1,%2,%3}, {%4,%5,%6,%7}, {%8,%9}, {%0,%1,%2,%3};"
        : "+f"(c[0]), "+f"(c[1]), "+f"(c[2]), "+f"(c[3])
        : "r"(a[0]), "r"(a[1]), "r"(a[2]), "r"(a[3]), "r"(b0), "r"(b1));
}

// ---------------- setup ------------------------------------------------------
__global__ void k_setup(const float* __restrict__ X, const int* __restrict__ ei,
                        const float* __restrict__ W0, const float* __restrict__ W1,
                        const float* __restrict__ W2, const float* __restrict__ Wo) {
    if (blockIdx.x >= 1280) {
        int i = (blockIdx.x - 1280) * 256 + threadIdx.x;
        const float* W; int K, Ncol, off, loc;
        if      (i < 65536)  { W = W0; K = 256; Ncol = 256; off = 0;      loc = i; }
        else if (i < 98304)  { W = W1; K = 128; Ncol = 256; off = 65536;  loc = i - 65536; }
        else if (i < 131072) { W = W2; K = 128; Ncol = 256; off = 98304;  loc = i - 98304; }
        else if (i < WTOT)   { W = Wo; K = 128; Ncol = 64;  off = 131072; loc = i - 131072; }
        else return;
        int n = loc / K, k = loc % K;
        g_Bt[off + n * K + k] = __float2half(W[k * Ncol + n]);
        return;
    }
    if (blockIdx.x >= 256) {
        int i = (blockIdx.x - 256) * 256 + threadIdx.x;
        int stride = 1024 * 256;
        for (int e = i; e < NE; e += stride)
            atomicAdd(&g_cnt[ei[NE + e]], 1);
        return;
    }
    int c = threadIdx.x, b = blockIdx.x;
    if (b == 0 && c < 6) (&g_asmax[0][0])[c] = 0;
    float s = 0.f;
    for (int r = b; r < NN; r += 256) {
        float v = X[(size_t)r * IND + c];
        g_A[(size_t)r * IND + c] = __float2half(v);
        s += v;
    }
    g_colpart[b * 256 + c] = s;
}

// ---------------- CSR scan + level-2 + vnode row -----------------------------
__global__ void k_scan1() {        // (SNB+1) x 1024
    if (blockIdx.x == SNB) {
        int c = threadIdx.x;
        if (c < 256) {
            float s = 0.f;
            for (int p = 0; p < 256; p++) s += g_colpart[p * 256 + c];
            g_A[(size_t)NN * IND + c] = __float2half(s * (1.0f / NN));
        }
        return;
    }
    int b = blockIdx.x, t = threadIdx.x, lane = t & 31, w = t >> 5;
    int idx = b * SCHUNK + t;
    int v = g_cnt[idx];
    g_cnt[idx] = 0;
    if (idx < NV) g_cur[idx] = 0;
    int x = v;
#pragma unroll
    for (int off = 1; off < 32; off <<= 1) {
        int y = __shfl_up_sync(0xffffffffu, x, off);
        if (lane >= off) x += y;
    }
    __shared__ int wt[32];
    if (lane == 31) wt[w] = x;
    __syncthreads();
    if (w == 0) {
        int z = wt[lane];
#pragma unroll
        for (int off = 1; off < 32; off <<= 1) {
            int y = __shfl_up_sync(0xffffffffu, z, off);
            if (lane >= off) z += y;
        }
        wt[lane] = z;
    }
    __syncthreads();
    int excl = x - v + (w ? wt[w - 1] : 0);
    g_scan[idx] = excl;
    if (t == 0) {
        g_btot[b] = wt[31];
        __threadfence();
        if (atomicAdd(&g_sdone, 1) == SNB - 1) {
            int acc = 0;
            for (int i = 0; i < SNB; i++) { g_boff[i] = acc; acc += g_btot[i]; }
            g_sdone = 0;
        }
    }
}

__device__ __forceinline__ int rowptr_of(int i) {
    return g_scan[i] + g_boff[i >> 10];
}

// ---------------- HMMA GEMM --------------------------------------------------
// HOUT path stores h with PERMUTED columns: feature f of head h goes to
// position (f>>2)*8 + h*4 + (f&3), so lane L's 8 agg values are 16B-contiguous.
template<int KTOT, int NTB, bool ALPHA, bool HOUT, bool FUSEFILL>
__global__ void __launch_bounds__(256, 2) k_hgemm(
    const __half* __restrict__ A, const __half* __restrict__ Bt,
    void* __restrict__ Cout, int M,
    const float* __restrict__ aws, const float* __restrict__ awd,
    const float* __restrict__ bias, uint32_t* __restrict__ asmax,
    const int* __restrict__ ei, int nblk)
{
    constexpr int NCH = KTOT / 64;
    constexpr int NTW = (NTB / 4) / 8;
    constexpr int NJP = NTW / 2;
    constexpr int STAGE = 8192 + NTB * 128;

    if (FUSEFILL && (int)blockIdx.x >= nblk) {
        int i = ((int)blockIdx.x - nblk) * 256 + threadIdx.x;
        int stride = 1024 * 256;
        for (int e = i; e < NE; e += stride) {
            int s = ei[e];
            int d = ei[NE + e];
            int pos = rowptr_of(d) + atomicAdd(&g_cur[d], 1);
            g_srcsorted[pos] = s;
        }
        return;
    }

    extern __shared__ char smem[];
    uint32_t sb = smem_to_u32(smem);
    int tid = threadIdx.x, wid = tid >> 5, lane = tid & 31;
    int wm = wid >> 2, wn = wid & 3;
    int row0 = blockIdx.x * 64;

    float acc[2][NTW][4];
#pragma unroll
    for (int mt = 0; mt < 2; mt++)
#pragma unroll
        for (int nt = 0; nt < NTW; nt++)
#pragma unroll
            for (int j = 0; j < 4; j++) acc[mt][nt][j] = 0.f;

    int lmrow = ((lane >> 3) & 1) * 8 + (lane & 7);
    uint32_t akoff = ((lane >> 4) & 1) * 16;
    int bnrow = wn * (NTB / 4) + ((lane >> 4) & 1) * 8 + (lane & 7);
    uint32_t bkoff = ((lane >> 3) & 1) * 16;

    for (int ch = 0; ch <= NCH; ch++) {
        if (ch < NCH) {
            uint32_t base = sb + (uint32_t)(ch & 1) * STAGE;
            for (int u = tid; u < 512; u += 256) {
                int r = u >> 3, c8 = u & 7;
                size_t gidx = (size_t)(row0 + r) * KTOT + ch * 64 + c8 * 8;
                CP16(base + SW128((uint32_t)(r * 128 + c8 * 16)), A + gidx);
            }
            for (int u = tid; u < NTB * 8; u += 256) {
                int r = u >> 3, c8 = u & 7;
                size_t gidx = (size_t)r * KTOT + ch * 64 + c8 * 8;
                CP16(base + 8192 + SW128((uint32_t)(r * 128 + c8 * 16)), Bt + gidx);
            }
            CPCOMMIT();
        }
        if (ch == 0) continue;
        if (ch < NCH) asm volatile("cp.async.wait_group 1;" ::: "memory");
        else         asm volatile("cp.async.wait_group 0;" ::: "memory");
        __syncthreads();
        uint32_t ab = sb + (uint32_t)((ch - 1) & 1) * STAGE;
#pragma unroll
        for (int ks = 0; ks < 4; ks++) {
            uint32_t ah[2][4];
#pragma unroll
            for (int mt = 0; mt < 2; mt++) {
                uint32_t aaddr = ab + SW128((uint32_t)((wm * 32 + mt * 16 + lmrow) * 128 + ks * 32 + akoff));
                LDSM_X4(ah[mt][0], ah[mt][1], ah[mt][2], ah[mt][3], aaddr);
            }
#pragma unroll
            for (int jp = 0; jp < NJP; jp++) {
                uint32_t baddr = ab + 8192 + SW128((uint32_t)((bnrow + jp * 16) * 128 + ks * 32 + bkoff));
                uint32_t b0, b1, b2, b3;
                LDSM_X4(b0, b1, b2, b3, baddr);
#pragma unroll
                for (int mt = 0; mt < 2; mt++) {
                    mma16816(acc[mt][2 * jp],     ah[mt], b0, b1);
                    mma16816(acc[mt][2 * jp + 1], ah[mt], b2, b3);
                }
            }
        }
        __syncthreads();
    }

    // ---- epilogue ----
    float* sAs = (float*)smem;          // [64][4]
    float* sAd = sAs + 256;             // [64][4]
    float* sMx = sAd + 256;             // [16]
    int g = lane >> 2, t = lane & 3;
#pragma unroll
    for (int mt = 0; mt < 2; mt++) {
        int r0 = wm * 32 + mt * 16 + g;
        int gr0 = row0 + r0, gr1 = gr0 + 8;
        float pa0 = 0.f, pa1 = 0.f, pd0 = 0.f, pd1 = 0.f;
#pragma unroll
        for (int nt = 0; nt < NTW; nt++) {
            int gc = wn * (NTB / 4) + nt * 8 + t * 2;
            float c0 = acc[mt][nt][0], c1 = acc[mt][nt][1];
            float c2 = acc[mt][nt][2], c3 = acc[mt][nt][3];
            if (!ALPHA) {
                float b0 = bias[gc], b1 = bias[gc + 1];
                c0 += b0; c1 += b1; c2 += b0; c3 += b1;
            }
            if (ALPHA) {
                float w0s = aws[gc], w1s = aws[gc + 1], w0d = awd[gc], w1d = awd[gc + 1];
                pa0 += c0 * w0s + c1 * w1s; pd0 += c0 * w0d + c1 * w1d;
                pa1 += c2 * w0s + c3 * w1s; pd1 += c2 * w0d + c3 * w1d;
            }
            if (HOUT) {
                // permuted store: f=gc&127, h=gc>>7 -> pos=(f>>2)*8 + h*4 + (f&3)
                int f = gc & 127, hh = gc >> 7;
                int pos = ((f >> 2) << 3) + (hh << 2) + (f & 3);
                __half* Ch = (__half*)Cout;
                if (gr0 < M) *(__half2*)(Ch + (size_t)gr0 * NTB + pos) = __floats2half2_rn(c0, c1);
                if (gr1 < M) *(__half2*)(Ch + (size_t)gr1 * NTB + pos) = __floats2half2_rn(c2, c3);
            } else {
                float* Cf = (float*)Cout;
                if (gr0 < M) *(float2*)(Cf + (size_t)gr0 * NTB + gc) = make_float2(c0, c1);
                if (gr1 < M) *(float2*)(Cf + (size_t)gr1 * NTB + gc) = make_float2(c2, c3);
            }
        }
        if (ALPHA) {
#pragma unroll
            for (int off = 1; off <= 2; off <<= 1) {
                pa0 += __shfl_xor_sync(0xffffffffu, pa0, off);
                pa1 += __shfl_xor_sync(0xffffffffu, pa1, off);
                pd0 += __shfl_xor_sync(0xffffffffu, pd0, off);
                pd1 += __shfl_xor_sync(0xffffffffu, pd1, off);
            }
            if (t == 0) {
                sAs[r0 * 4 + wn] = pa0; sAs[(r0 + 8) * 4 + wn] = pa1;
                sAd[r0 * 4 + wn] = pd0; sAd[(r0 + 8) * 4 + wn] = pd1;
            }
        }
    }
    if (ALPHA) {
        __syncthreads();
        float lm0 = -3.4e38f, lm1 = -3.4e38f;
        if (tid < 64) {
            int row = row0 + tid;
            float as0 = sAs[tid * 4 + 0] + sAs[tid * 4 + 1];
            float as1 = sAs[tid * 4 + 2] + sAs[tid * 4 + 3];
            float ad0 = sAd[tid * 4 + 0] + sAd[tid * 4 + 1];
            float ad1 = sAd[tid * 4 + 2] + sAd[tid * 4 + 3];
            if (row < M) {
                g_as[2 * row] = as0; g_as[2 * row + 1] = as1;
                g_ad[2 * row] = ad0; g_ad[2 * row + 1] = ad1;
                lm0 = as0; lm1 = as1;
            }
        }
#pragma unroll
        for (int off = 16; off; off >>= 1) {
            lm0 = fmaxf(lm0, __shfl_xor_sync(0xffffffffu, lm0, off));
            lm1 = fmaxf(lm1, __shfl_xor_sync(0xffffffffu, lm1, off));
        }
        if (lane == 0 && wid < 2) { sMx[wid] = lm0; sMx[8 + wid] = lm1; }
        __syncthreads();
        if (tid == 0) {
            float m0 = fmaxf(sMx[0], sMx[1]);
            float m1 = fmaxf(sMx[8], sMx[9]);
            atomicMax(asmax + 0, fkey(m0));
            atomicMax(asmax + 1, fkey(m1));
        }
    }
}

// ---------------- merged vnode + node aggregation ----------------------------
// Round-15 scheduling (per-edge exp + explicit prefetch), permuted h layout:
// uint4 at (node*C2 + 8*lane): x,y = head0 f(4L..4L+3), z,w = head1.
#define VB 256
__global__ void k_agg(int l, const float* __restrict__ b,
                      const float* __restrict__ gam, const float* __restrict__ bet) {
    int tid = threadIdx.x, wid = tid >> 5, lane = tid & 31;
    float m0g = funkey(g_asmax[l][0]), m1g = funkey(g_asmax[l][1]);

    if (blockIdx.x < VB) {
        float adv0 = g_ad[2 * NN], adv1 = g_ad[2 * NN + 1];
        float adl0 = adv0 * L2E, adl1 = adv1 * L2E;
        float mlog0 = lrelu(m0g + adv0) * L2E, mlog1 = lrelu(m1g + adv1) * L2E;
        int gw = blockIdx.x * 8 + wid;
        u64 A0 = 0, A1 = 0, A2 = 0, A3 = 0;
        float den0 = 0.f, den1 = 0.f;
        for (int j = gw; j < NV; j += VB * 8) {
            float t0 = fmaf(g_as[2 * j], L2E, adl0);
            float t1 = fmaf(g_as[2 * j + 1], L2E, adl1);
            t0 = fmaxf(t0, 0.2f * t0); t1 = fmaxf(t1, 0.2f * t1);
            float e0 = ex2f(t0 - mlog0), e1 = ex2f(t1 - mlog1);
            den0 += e0; den1 += e1;
            u64 C0 = pk2(e0, e0), C1 = pk2(e1, e1);
            uint4 u = *(const uint4*)(g_hh + (size_t)j * C2 + 8 * lane);
            fma2p(A0, h2f2(u.x), C0); fma2p(A1, h2f2(u.y), C0);
            fma2p(A2, h2f2(u.z), C1); fma2p(A3, h2f2(u.w), C1);
        }
        float a0x, a0y, a0z, a0w, a1x, a1y, a1z, a1w;
        upk2(A0, a0x, a0y); upk2(A1, a0z, a0w);
        upk2(A2, a1x, a1y); upk2(A3, a1z, a1w);
        __shared__ float buf[C2];
        __shared__ float sden[2];
        if (tid < C2) buf[tid] = 0.f;
        if (tid < 2) sden[tid] = 0.f;
        __syncthreads();
        atomicAdd(&buf[4 * lane + 0], a0x); atomicAdd(&buf[4 * lane + 1], a0y);
        atomicAdd(&buf[4 * lane + 2], a0z); atomicAdd(&buf[4 * lane + 3], a0w);
        atomicAdd(&buf[128 + 4 * lane + 0], a1x); atomicAdd(&buf[128 + 4 * lane + 1], a1y);
        atomicAdd(&buf[128 + 4 * lane + 2], a1z); atomicAdd(&buf[128 + 4 * lane + 3], a1w);
        if (lane == 0) { atomicAdd(&sden[0], den0); atomicAdd(&sden[1], den1); }
        __syncthreads();
        if (tid < C2) atomicAdd(&g_vS[tid], buf[tid]);
        if (tid < 2) atomicAdd(&g_vden[tid], sden[tid]);

        __threadfence();
        __shared__ int slast;
        if (tid == 0) slast = (atomicAdd(&g_vdone, 1) == VB - 1);
        __syncthreads();
        if (!slast) return;

        int o = tid;
        float v = 0.f;
        if (o < 128) {
            float d0 = g_vden[0] + 1e-16f, d1 = g_vden[1] + 1e-16f;
            v = 0.5f * (g_vS[o] / d0 + g_vS[HID + o] / d1) + b[o];
        }
        __shared__ float ssum[8], ssq[8];
        float ls = (o < 128) ? v : 0.f, lq = (o < 128) ? v * v : 0.f;
#pragma unroll
        for (int off = 16; off; off >>= 1) {
            ls += __shfl_xor_sync(0xffffffffu, ls, off);
            lq += __shfl_xor_sync(0xffffffffu, lq, off);
        }
        if (lane == 0) { ssum[wid] = ls; ssq[wid] = lq; }
        __syncthreads();
        float ts = ssum[0] + ssum[1] + ssum[2] + ssum[3];
        float tq = ssq[0] + ssq[1] + ssq[2] + ssq[3];
        float mu = ts * (1.0f / HID);
        float var = tq * (1.0f / HID) - mu * mu;
        if (o < 128) {
            float y = (v - mu) * rsqrtf(var + 1e-5f) * gam[o] + bet[o];
            y = 0.5f * y * (1.f + erff(y * 0.70710678118654752f));
            g_A[(size_t)NN * HID + o] = __float2half(y);
        }
        __syncthreads();
        if (o < C2) g_vS[o] = 0.f;
        if (o < 2) g_vden[o] = 0.f;
        if (o == 0) g_vdone = 0;
        return;
    }

    int i = (blockIdx.x - VB) * 8 + wid;
    if (i >= NN) return;
    float ad0 = g_ad[2 * i], ad1 = g_ad[2 * i + 1];
    float adl0 = ad0 * L2E, adl1 = ad1 * L2E;
    float mlog0 = lrelu(m0g + ad0) * L2E, mlog1 = lrelu(m1g + ad1) * L2E;

    u64 A0 = 0, A1 = 0, A2 = 0, A3 = 0;
    float den0, den1;
    {
        // self loop
        float t0 = fmaf(g_as[2 * i], L2E, adl0);
        float t1 = fmaf(g_as[2 * i + 1], L2E, adl1);
        t0 = fmaxf(t0, 0.2f * t0); t1 = fmaxf(t1, 0.2f * t1);
        float c0 = ex2f(t0 - mlog0), c1 = ex2f(t1 - mlog1);
        den0 = c0; den1 = c1;
        u64 C0 = pk2(c0, c0), C1 = pk2(c1, c1);
        uint4 u = *(const uint4*)(g_hh + (size_t)i * C2 + 8 * lane);
        fma2p(A0, h2f2(u.x), C0); fma2p(A1, h2f2(u.y), C0);
        fma2p(A2, h2f2(u.z), C1); fma2p(A3, h2f2(u.w), C1);
        // vnode -> node edge
        t0 = fmaf(g_as[2 * NN], L2E, adl0);
        t1 = fmaf(g_as[2 * NN + 1], L2E, adl1);
        t0 = fmaxf(t0, 0.2f * t0); t1 = fmaxf(t1, 0.2f * t1);
        c0 = ex2f(t0 - mlog0); c1 = ex2f(t1 - mlog1);
        den0 += c0; den1 += c1;
        C0 = pk2(c0, c0); C1 = pk2(c1, c1);
        uint4 uv = *(const uint4*)(g_hh + (size_t)NN * C2 + 8 * lane);
        fma2p(A0, h2f2(uv.x), C0); fma2p(A1, h2f2(uv.y), C0);
        fma2p(A2, h2f2(uv.z), C1); fma2p(A3, h2f2(uv.w), C1);
    }
    int beg = rowptr_of(i), end = rowptr_of(i + 1);
    if (beg < end) {
        // software pipeline: prefetch src id, alpha, AND h uint4 one edge ahead
        int s = g_srcsorted[beg];
        float as0 = g_as[2 * s], as1 = g_as[2 * s + 1];
        uint4 u = *(const uint4*)(g_hh + (size_t)s * C2 + 8 * lane);
        for (int e = beg; e < end; e++) {
            float ca0 = as0, ca1 = as1;
            uint4 cu = u;
            if (e + 1 < end) {
                int sn = g_srcsorted[e + 1];
                as0 = g_as[2 * sn]; as1 = g_as[2 * sn + 1];
                u = *(const uint4*)(g_hh + (size_t)sn * C2 + 8 * lane);
            }
            float t0 = fmaf(ca0, L2E, adl0);
            float t1 = fmaf(ca1, L2E, adl1);
            t0 = fmaxf(t0, 0.2f * t0); t1 = fmaxf(t1, 0.2f * t1);
            float c0 = ex2f(t0 - mlog0), c1 = ex2f(t1 - mlog1);
            den0 += c0; den1 += c1;
            u64 C0 = pk2(c0, c0), C1 = pk2(c1, c1);
            fma2p(A0, h2f2(cu.x), C0); fma2p(A1, h2f2(cu.y), C0);
            fma2p(A2, h2f2(cu.z), C1); fma2p(A3, h2f2(cu.w), C1);
        }
    }

    float a0x, a0y, a0z, a0w, a1x, a1y, a1z, a1w;
    upk2(A0, a0x, a0y); upk2(A1, a0z, a0w);
    upk2(A2, a1x, a1y); upk2(A3, a1z, a1w);

    float inv0 = 0.5f / (den0 + 1e-16f);
    float inv1 = 0.5f / (den1 + 1e-16f);
    float v[4];
    v[0] = a0x * inv0 + a1x * inv1;
    v[1] = a0y * inv0 + a1y * inv1;
    v[2] = a0z * inv0 + a1z * inv1;
    v[3] = a0w * inv0 + a1w * inv1;
    float lsum = 0.f, lsq = 0.f;
#pragma unroll
    for (int r = 0; r < 4; r++) {
        int o = 4 * lane + r;
        v[r] += b[o];
        lsum += v[r];
        lsq = fmaf(v[r], v[r], lsq);
    }
#pragma unroll
    for (int off = 16; off; off >>= 1) {
        lsum += __shfl_xor_sync(0xffffffffu, lsum, off);
        lsq += __shfl_xor_sync(0xffffffffu, lsq, off);
    }
    float mu = lsum * (1.0f / HID);
    float var = lsq * (1.0f / HID) - mu * mu;
    float rstd = rsqrtf(var + 1e-5f);
    __half hs[4];
#pragma unroll
    for (int r = 0; r < 4; r++) {
        int o = 4 * lane + r;
        float y = (v[r] - mu) * rstd * gam[o] + bet[o];
        y = 0.5f * y * (1.f + erff(y * 0.70710678118654752f));
        hs[r] = __float2half(y);
    }
    *(uint2*)&g_A[(size_t)i * HID + 4 * lane] = *(uint2*)hs;
}

// ---------------- host orchestration ----------------------------------------
extern "C" void kernel_launch(void* const* d_in, const int* in_sizes, int n_in,
                              void* d_out, int out_size) {
    const float* X  = (const float*)d_in[0];
    const int*   ei = (const int*)d_in[1];
    const float* W[3]   = { (const float*)d_in[3],  (const float*)d_in[9],  (const float*)d_in[15] };
    const float* a_s[3] = { (const float*)d_in[4],  (const float*)d_in[10], (const float*)d_in[16] };
    const float* a_d[3] = { (const float*)d_in[5],  (const float*)d_in[11], (const float*)d_in[17] };
    const float* bb[3]  = { (const float*)d_in[6],  (const float*)d_in[12], (const float*)d_in[18] };
    const float* gg[3]  = { (const float*)d_in[7],  (const float*)d_in[13], (const float*)d_in[19] };
    const float* be[3]  = { (const float*)d_in[8],  (const float*)d_in[14], (const float*)d_in[20] };
    const float* Wout = (const float*)d_in[21];
    const float* bout = (const float*)d_in[22];

    __half *pA, *pBt, *p_hh;
    uint32_t* p_am;
    cudaGetSymbolAddress((void**)&pA,   g_A);
    cudaGetSymbolAddress((void**)&pBt,  g_Bt);
    cudaGetSymbolAddress((void**)&p_hh, g_hh);
    cudaGetSymbolAddress((void**)&p_am, g_asmax);

    const int SM256 = 2 * (8192 + 256 * 128);   // 81920
    const int SM64  = 2 * (8192 + 64 * 128);    // 32768
    cudaFuncSetAttribute(k_hgemm<256, 256, true,  true,  true>,  cudaFuncAttributeMaxDynamicSharedMemorySize, SM256);
    cudaFuncSetAttribute(k_hgemm<128, 256, true,  true,  false>, cudaFuncAttributeMaxDynamicSharedMemorySize, SM256);
    cudaFuncSetAttribute(k_hgemm<128, 64,  false, false, false>, cudaFuncAttributeMaxDynamicSharedMemorySize, SM64);

    const int NBLK = NPAD / 64;           // 782
    const int AGGB = VB + (NN + 7) / 8;   // 6506
    const int WOFF[4] = { 0, 65536, 98304, 131072 };

    k_setup<<<1825, 256>>>(X, ei, W[0], W[1], W[2], Wout);   // idx 0
    k_scan1<<<SNB + 1, 1024>>>();                            // idx 1
    // layer-0 GEMM fused with CSR fill
    k_hgemm<256, 256, true, true, true><<<NBLK + 1024, 256, SM256>>>(
        pA, pBt + WOFF[0], p_hh, NV, a_s[0], a_d[0], nullptr, p_am + 0, ei, NBLK);  // idx 2
    k_agg<<<AGGB, 256>>>(0, bb[0], gg[0], be[0]);            // idx 3 == profiled

    for (int l = 1; l < 3; l++) {
        k_hgemm<128, 256, true, true, false><<<NBLK, 256, SM256>>>(
            pA, pBt + WOFF[l], p_hh, NV, a_s[l], a_d[l], nullptr, p_am + 2 * l, nullptr, NBLK);
        k_agg<<<AGGB, 256>>>(l, bb[l], gg[l], be[l]);
    }

    k_hgemm<128, 64, false, false, false><<<NBLK, 256, SM64>>>(
        pA, pBt + WOFF[3], (float*)d_out, NN, nullptr, nullptr, bout, nullptr, nullptr, NBLK);
}